// round 2
// baseline (speedup 1.0000x reference)
#include <cuda_runtime.h>
#include <math.h>

// Problem constants
#define B_ 2
#define L_ 2048
#define D_ 2048
#define H_ 8
#define HD_ 256
#define FD_ 64
#define FEAT_ 128          // 2*FD
#define CHUNK_ 64
#define NCH_ (L_/CHUNK_)   // 32
#define HALF_ (HD_/2)      // 128

// ---------------- scratch (device globals; no allocation allowed) ----------
__device__ float g_q [B_*L_*H_*HD_];          // [b,l,h,d]   33.5 MB
__device__ float g_k [B_*L_*HD_];             // [b,l,d]      4 MB
__device__ float g_v [B_*L_*HD_];             // [b,l,d]      4 MB
__device__ float g_qf[B_*H_*L_*FEAT_];        // [b,h,l,f]   16.8 MB
__device__ float g_kf[B_*H_*L_*FEAT_];        // [b,h,l,f]   16.8 MB
__device__ float g_kv[B_*H_*NCH_*FEAT_*HD_];  // [bh,n,f,d]  64 MB
__device__ float g_o [B_*L_*H_*HD_];          // [b,l,h*d]   33.5 MB

// ---------------- SGEMM: C[M,N] = A[M,K] * B[K,N], fp32, row-major --------
#define BM 128
#define BN 128
#define BK 16
#define TM 8
#define TN 8

__global__ __launch_bounds__(256)
void sgemm_kernel(int M, int N, int K,
                  const float* __restrict__ A,
                  const float* __restrict__ Bm,
                  float* __restrict__ C) {
    const int cRow = blockIdx.y, cCol = blockIdx.x;
    const int tCol = threadIdx.x % (BN/TN);   // 0..15
    const int tRow = threadIdx.x / (BN/TN);   // 0..15

    __shared__ float As[BK][BM];
    __shared__ float Bs[BK][BN];

    A  += (size_t)cRow*BM*K;
    Bm += cCol*BN;
    C  += (size_t)cRow*BM*N + cCol*BN;

    const int innerRowA = threadIdx.x / (BK/4);       // 0..63
    const int innerColA = (threadIdx.x % (BK/4))*4;   // 0,4,8,12
    const int strideA   = 256/(BK/4);                 // 64
    const int innerRowB = threadIdx.x / (BN/4);       // 0..7
    const int innerColB = (threadIdx.x % (BN/4))*4;
    const int strideB   = 256/(BN/4);                 // 8

    float acc[TM][TN];
    #pragma unroll
    for (int m = 0; m < TM; m++)
        #pragma unroll
        for (int n = 0; n < TN; n++) acc[m][n] = 0.f;

    float regM[TM], regN[TN];

    for (int k0 = 0; k0 < K; k0 += BK) {
        #pragma unroll
        for (int r = innerRowA; r < BM; r += strideA) {
            float4 t = *(const float4*)&A[(size_t)r*K + innerColA];
            As[innerColA+0][r] = t.x;
            As[innerColA+1][r] = t.y;
            As[innerColA+2][r] = t.z;
            As[innerColA+3][r] = t.w;
        }
        #pragma unroll
        for (int r = innerRowB; r < BK; r += strideB) {
            *(float4*)&Bs[r][innerColB] = *(const float4*)&Bm[(size_t)r*N + innerColB];
        }
        __syncthreads();
        A  += BK;
        Bm += (size_t)BK*N;

        #pragma unroll
        for (int kk = 0; kk < BK; kk++) {
            #pragma unroll
            for (int m = 0; m < TM; m++) regM[m] = As[kk][tRow*TM+m];
            #pragma unroll
            for (int n = 0; n < TN; n++) regN[n] = Bs[kk][tCol*TN+n];
            #pragma unroll
            for (int m = 0; m < TM; m++)
                #pragma unroll
                for (int n = 0; n < TN; n++)
                    acc[m][n] += regM[m]*regN[n];
        }
        __syncthreads();
    }

    #pragma unroll
    for (int m = 0; m < TM; m++) {
        #pragma unroll
        for (int n = 0; n < TN; n += 4) {
            float4 t = make_float4(acc[m][n], acc[m][n+1], acc[m][n+2], acc[m][n+3]);
            *(float4*)&C[(size_t)(tRow*TM+m)*N + tCol*TN + n] = t;
        }
    }
}

// ---------------- RoPE (in place) -----------------------------------------
__global__ void rope_kernel(float* __restrict__ x,
                            const float* __restrict__ cs,
                            const float* __restrict__ sn,
                            int heads) {
    int idx = blockIdx.x*blockDim.x + threadIdx.x;
    int total = B_*L_*heads*HALF_;
    if (idx >= total) return;
    int j = idx % HALF_;
    int h = (idx / HALF_) % heads;
    int l = (idx / (HALF_*heads)) % L_;
    int b =  idx / (HALF_*heads*L_);
    float c = cs[l*HALF_ + j];
    float s = sn[l*HALF_ + j];
    float* row = x + ((size_t)(b*L_ + l)*heads + h)*HD_;
    float x1 = row[j], x2 = row[j + HALF_];
    row[j]        = x1*c - x2*s;
    row[j + HALF_] = x1*s + x2*c;
}

// ---------------- Hedgehog feature map ------------------------------------
// out[b,h,l,f] = softmax over concat([p,-p]) where p[f]=sum_d x[b,l,(xh==1?0:h),d]*fm[h,d,f]
__global__ __launch_bounds__(256)
void hedgehog_kernel(const float* __restrict__ x,
                     const float* __restrict__ fm,
                     float* __restrict__ outf,
                     int xh, float scale) {
    __shared__ float xs[16][HD_];   // 16 KB
    __shared__ float ps[16][FD_];   // 4 KB
    __shared__ float ms[16], zs[16];

    int h = blockIdx.y, b = blockIdx.z;
    int l0 = blockIdx.x * 16;
    int t = threadIdx.x;
    int srcH = (xh == 1) ? 0 : h;

    for (int e = t; e < 16*HD_; e += 256) {
        int r = e / HD_, d = e % HD_;
        xs[r][d] = x[((size_t)(b*L_ + l0 + r)*xh + srcH)*HD_ + d];
    }
    __syncthreads();

    int r  = t / 16;
    int fb = (t % 16) * 4;
    float a0=0.f, a1=0.f, a2=0.f, a3=0.f;
    const float* fmh = fm + (size_t)h*HD_*FD_;
    #pragma unroll 4
    for (int d = 0; d < HD_; d++) {
        float xv = xs[r][d];
        float4 w = *(const float4*)&fmh[d*FD_ + fb];
        a0 += xv*w.x; a1 += xv*w.y; a2 += xv*w.z; a3 += xv*w.w;
    }
    ps[r][fb+0]=a0; ps[r][fb+1]=a1; ps[r][fb+2]=a2; ps[r][fb+3]=a3;
    __syncthreads();

    if (t < 16) {
        float m = 0.f;
        for (int f = 0; f < FD_; f++) m = fmaxf(m, fabsf(ps[t][f]));
        float z = 0.f;
        for (int f = 0; f < FD_; f++)
            z += __expf(ps[t][f] - m) + __expf(-ps[t][f] - m);
        ms[t] = m; zs[t] = z;
    }
    __syncthreads();

    for (int e = t; e < 16*FEAT_; e += 256) {
        int rr = e / FEAT_, f = e % FEAT_;
        float p = (f < FD_) ? ps[rr][f] : -ps[rr][f - FD_];
        float val = __expf(p - ms[rr]) / zs[rr] * scale;
        outf[((size_t)(b*H_ + h)*L_ + l0 + rr)*FEAT_ + f] = val;
    }
}

// ---------------- per-chunk kv state: kv[f,d] = sum_c kf[c,f]*v[c,d] ------
__global__ __launch_bounds__(256)
void kv_kernel(const float* __restrict__ kf, const float* __restrict__ v,
               float* __restrict__ kv) {
    __shared__ float ks[CHUNK_][FEAT_];  // 32 KB
    __shared__ float vs[CHUNK_][64];     // 16 KB
    int n  = blockIdx.x;
    int dt = blockIdx.y;        // 0..3 (64-wide d tile)
    int bh = blockIdx.z;
    int b  = bh / H_;
    int t  = threadIdx.x;

    const float* kfp = kf + ((size_t)bh*L_ + n*CHUNK_)*FEAT_;
    for (int e = t; e < CHUNK_*FEAT_; e += 256) ks[e/FEAT_][e%FEAT_] = kfp[e];
    const float* vp = v + ((size_t)b*L_ + n*CHUNK_)*HD_ + dt*64;
    for (int e = t; e < CHUNK_*64; e += 256) vs[e/64][e%64] = vp[(size_t)(e/64)*HD_ + (e%64)];
    __syncthreads();

    int dd = t % 64;
    int f0 = t / 64;  // 0..3
    float acc[32];
    #pragma unroll
    for (int i = 0; i < 32; i++) acc[i] = 0.f;

    for (int c = 0; c < CHUNK_; c++) {
        float vv = vs[c][dd];
        #pragma unroll
        for (int i = 0; i < 32; i++) acc[i] += ks[c][f0 + i*4]*vv;
    }

    float* out = kv + ((size_t)(bh*NCH_ + n)*FEAT_)*HD_ + dt*64;
    #pragma unroll
    for (int i = 0; i < 32; i++) {
        int f = f0 + i*4;
        out[(size_t)f*HD_ + dd] = acc[i];
    }
}

// ---------------- exclusive cumsum over chunk axis (in place) -------------
__global__ void cumsum_kernel(float* __restrict__ kv) {
    int bh = blockIdx.y;
    int e  = blockIdx.x*256 + threadIdx.x;    // 0..32767  (f*256+d)
    float* base = kv + (size_t)bh*NCH_*FEAT_*HD_ + e;
    float run = 0.f;
    for (int n = 0; n < NCH_; n++) {
        float tmp = base[(size_t)n*FEAT_*HD_];
        base[(size_t)n*FEAT_*HD_] = run;
        run += tmp;
    }
}

// ---------------- inter + intra chunk attention ---------------------------
// o[b, l, h*HD + j] = q_chunk @ KVprev + tril(q k^T) @ v
__global__ __launch_bounds__(256)
void attn_kernel(const float* __restrict__ qf, const float* __restrict__ kf,
                 const float* __restrict__ v,  const float* __restrict__ kv,
                 float* __restrict__ o) {
    __shared__ float qs[CHUNK_][FEAT_];    // 32 KB
    __shared__ float ss[CHUNK_][CHUNK_];   // 16 KB
    int n = blockIdx.x, h = blockIdx.y, b = blockIdx.z;
    int bh = b*H_ + h;
    int t = threadIdx.x;
    int j = t;                             // output column 0..255

    const float* qp = qf + ((size_t)bh*L_ + n*CHUNK_)*FEAT_;
    for (int e = t; e < CHUNK_*FEAT_; e += 256) qs[e/FEAT_][e%FEAT_] = qp[e];
    __syncthreads();

    float acc[CHUNK_];
    #pragma unroll
    for (int i = 0; i < CHUNK_; i++) acc[i] = 0.f;

    // Phase A: inter = q @ KVprev  (stream kv rows, float4 q loads)
    const float* kvp = kv + ((size_t)(bh*NCH_ + n)*FEAT_)*HD_;
    for (int f = 0; f < FEAT_; f += 4) {
        float k0 = kvp[(size_t)(f+0)*HD_ + j];
        float k1 = kvp[(size_t)(f+1)*HD_ + j];
        float k2 = kvp[(size_t)(f+2)*HD_ + j];
        float k3 = kvp[(size_t)(f+3)*HD_ + j];
        #pragma unroll
        for (int i = 0; i < CHUNK_; i++) {
            float4 qv = *(const float4*)&qs[i][f];
            acc[i] += qv.x*k0 + qv.y*k1 + qv.z*k2 + qv.w*k3;
        }
    }

    // Phase B: s = tril(q @ k^T)
    {
        const float* kp = kf + ((size_t)bh*L_ + n*CHUNK_)*FEAT_;
        int i   = t / 4;
        int jp0 = (t % 4) * 16;
        for (int jj = 0; jj < 16; jj++) {
            int jp = jp0 + jj;
            float sum = 0.f;
            if (jp <= i) {
                const float* krow = kp + (size_t)jp*FEAT_;
                #pragma unroll 8
                for (int f = 0; f < FEAT_; f += 4) {
                    float4 qv = *(const float4*)&qs[i][f];
                    float4 kr = *(const float4*)&krow[f];
                    sum += qv.x*kr.x + qv.y*kr.y + qv.z*kr.z + qv.w*kr.w;
                }
            }
            ss[i][jp] = sum;
        }
    }
    __syncthreads();

    // Phase C: intra = s @ v_chunk
    const float* vp = v + ((size_t)b*L_ + n*CHUNK_)*HD_;
    for (int jp = 0; jp < CHUNK_; jp += 4) {
        float v0 = vp[(size_t)(jp+0)*HD_ + j];
        float v1 = vp[(size_t)(jp+1)*HD_ + j];
        float v2 = vp[(size_t)(jp+2)*HD_ + j];
        float v3 = vp[(size_t)(jp+3)*HD_ + j];
        #pragma unroll
        for (int i = 0; i < CHUNK_; i++) {
            float4 sv = *(const float4*)&ss[i][jp];
            acc[i] += sv.x*v0 + sv.y*v1 + sv.z*v2 + sv.w*v3;
        }
    }

    float* op = o + ((size_t)(b*L_ + n*CHUNK_))*(H_*HD_) + h*HD_ + j;
    #pragma unroll
    for (int i = 0; i < CHUNK_; i++) op[(size_t)i*(H_*HD_)] = acc[i];
}

// ---------------- launch ---------------------------------------------------
extern "C" void kernel_launch(void* const* d_in, const int* in_sizes, int n_in,
                              void* d_out, int out_size) {
    const float* hidden = (const float*)d_in[0];
    const float* fcos   = (const float*)d_in[1];
    const float* fsin   = (const float*)d_in[2];
    // d_in[3] = mask (unused by reference math)
    const float* Wq     = (const float*)d_in[4];
    const float* Wk     = (const float*)d_in[5];
    const float* Wv     = (const float*)d_in[6];
    const float* Wo     = (const float*)d_in[7];
    const float* fmq    = (const float*)d_in[8];
    const float* fmk    = (const float*)d_in[9];
    float* out          = (float*)d_out;

    float *q, *k, *v, *qf, *kf, *kv, *o;
    cudaGetSymbolAddress((void**)&q,  g_q);
    cudaGetSymbolAddress((void**)&k,  g_k);
    cudaGetSymbolAddress((void**)&v,  g_v);
    cudaGetSymbolAddress((void**)&qf, g_qf);
    cudaGetSymbolAddress((void**)&kf, g_kf);
    cudaGetSymbolAddress((void**)&kv, g_kv);
    cudaGetSymbolAddress((void**)&o,  g_o);

    const int M = B_*L_;   // 4096

    // 1) projections
    sgemm_kernel<<<dim3(D_/BN,     M/BM), 256>>>(M, H_*HD_, D_, hidden, Wq, q);
    sgemm_kernel<<<dim3(HD_/BN,    M/BM), 256>>>(M, HD_,    D_, hidden, Wk, k);
    sgemm_kernel<<<dim3(HD_/BN,    M/BM), 256>>>(M, HD_,    D_, hidden, Wv, v);

    // 2) RoPE
    {
        int totq = B_*L_*H_*HALF_;
        rope_kernel<<<(totq + 255)/256, 256>>>(q, fcos, fsin, H_);
        int totk = B_*L_*1*HALF_;
        rope_kernel<<<(totk + 255)/256, 256>>>(k, fcos, fsin, 1);
    }

    // 3) hedgehog feature maps (q scaled by feat^-0.5 = 1/sqrt(128))
    const float qscale = 0.08838834764831845f;   // 128^-0.5
    hedgehog_kernel<<<dim3(L_/16, H_, B_), 256>>>(q, fmq, qf, H_, qscale);
    hedgehog_kernel<<<dim3(L_/16, H_, B_), 256>>>(k, fmk, kf, 1, 1.0f);

    // 4) chunk kv states + exclusive cumsum
    kv_kernel<<<dim3(NCH_, 4, B_*H_), 256>>>(kf, v, kv);
    cumsum_kernel<<<dim3(128, B_*H_), 256>>>(kv);

    // 5) inter + intra attention
    attn_kernel<<<dim3(NCH_, H_, B_), 256>>>(qf, kf, v, kv, o);

    // 6) output projection
    sgemm_kernel<<<dim3(D_/BN, M/BM), 256>>>(M, D_, H_*HD_, o, Wo, out);
}

// round 3
// speedup vs baseline: 1.2287x; 1.2287x over previous
#include <cuda_runtime.h>
#include <math.h>
#include <stdint.h>

// Problem constants
#define B_ 2
#define L_ 2048
#define D_ 2048
#define H_ 8
#define HD_ 256
#define FD_ 64
#define FEAT_ 128          // 2*FD
#define CHUNK_ 64
#define NCH_ (L_/CHUNK_)   // 32
#define HALF_ (HD_/2)      // 128

// ---------------- scratch (device globals; no allocation allowed) ----------
__device__ float g_q [B_*L_*H_*HD_];          // [b,l,h,d]   33.5 MB
__device__ float g_k [B_*L_*HD_];             // [b,l,d]      4 MB
__device__ float g_v [B_*L_*HD_];             // [b,l,d]      4 MB
__device__ float g_qf[B_*H_*L_*FEAT_];        // [b,h,l,f]   16.8 MB
__device__ float g_kf[B_*H_*L_*FEAT_];        // [b,h,l,f]   16.8 MB
__device__ float g_kv[B_*H_*NCH_*FEAT_*HD_];  // [bh,n,f,d]  64 MB
__device__ float g_o [B_*L_*H_*HD_];          // [b,l,h*d]   33.5 MB

// ============================================================================
// TF32 tensor-core GEMM with 3xTF32 split (fp32-quality results)
// C[M,N] = A[M,K] * B[K,N], all row-major fp32.
// Tile: 128x128x16, 8 warps (2x4), warp tile 64x32, mma m16n8k8.
// ============================================================================

__device__ __forceinline__ uint32_t f2tf32(float x) {
    uint32_t r;
    asm("cvt.rna.tf32.f32 %0, %1;" : "=r"(r) : "f"(x));
    return r;
}

__device__ __forceinline__ void mma_tf32(float* d,
                                         const uint32_t* a,
                                         const uint32_t* b) {
    asm volatile(
        "mma.sync.aligned.m16n8k8.row.col.f32.tf32.tf32.f32 "
        "{%0,%1,%2,%3}, {%4,%5,%6,%7}, {%8,%9}, {%0,%1,%2,%3};\n"
        : "+f"(d[0]), "+f"(d[1]), "+f"(d[2]), "+f"(d[3])
        : "r"(a[0]), "r"(a[1]), "r"(a[2]), "r"(a[3]),
          "r"(b[0]), "r"(b[1]));
}

__device__ __forceinline__ void cp16(void* smem_dst, const void* gmem_src) {
    uint32_t s = (uint32_t)__cvta_generic_to_shared(smem_dst);
    asm volatile("cp.async.ca.shared.global [%0], [%1], 16;\n"
                 :: "r"(s), "l"(gmem_src));
}
__device__ __forceinline__ void cp_commit() {
    asm volatile("cp.async.commit_group;\n");
}

#define APAD 4    // As row stride = 20 floats (conflict-free fragment loads)
#define BPAD 8    // Bs row stride = 136 floats

__global__ __launch_bounds__(256)
void tf32gemm_kernel(int M, int N, int K,
                     const float* __restrict__ A,
                     const float* __restrict__ Bm,
                     float* __restrict__ C) {
    __shared__ float As[2][128][16 + APAD];
    __shared__ float Bs[2][16][128 + BPAD];

    const int tid  = threadIdx.x;
    const int lane = tid & 31;
    const int warp = tid >> 5;
    const int warpM = warp & 1;       // 0..1  -> 64 rows each
    const int warpN = warp >> 1;      // 0..3  -> 32 cols each
    const int g  = lane >> 2;         // 0..7
    const int t4 = lane & 3;          // 0..3

    const int cRow = blockIdx.y, cCol = blockIdx.x;
    A  += (size_t)cRow * 128 * K;
    Bm += cCol * 128;
    C  += (size_t)cRow * 128 * N + cCol * 128;

    // global->smem copy indices (each thread: 2 float4 of A, 2 float4 of B)
    const int ar = tid >> 2;            // 0..63
    const int ac = (tid & 3) * 4;       // 0,4,8,12
    const int bk = tid >> 5;            // 0..7
    const int bn = (tid & 31) * 4;      // 0..124

    float acc[4][4][4];
    #pragma unroll
    for (int mt = 0; mt < 4; mt++)
        #pragma unroll
        for (int nt = 0; nt < 4; nt++)
            #pragma unroll
            for (int i = 0; i < 4; i++) acc[mt][nt][i] = 0.f;

    const int KT = K >> 4;

    // prologue: stage 0
    {
        const float* Ap = A;
        const float* Bp = Bm;
        cp16(&As[0][ar][ac],      Ap + (size_t)ar * K + ac);
        cp16(&As[0][ar + 64][ac], Ap + (size_t)(ar + 64) * K + ac);
        cp16(&Bs[0][bk][bn],      Bp + (size_t)bk * N + bn);
        cp16(&Bs[0][bk + 8][bn],  Bp + (size_t)(bk + 8) * N + bn);
        cp_commit();
    }

    for (int kt = 0; kt < KT; kt++) {
        if (kt + 1 < KT) {
            const int s = (kt + 1) & 1;
            const int k0 = (kt + 1) << 4;
            const float* Ap = A + k0;
            const float* Bp = Bm + (size_t)k0 * N;
            cp16(&As[s][ar][ac],      Ap + (size_t)ar * K + ac);
            cp16(&As[s][ar + 64][ac], Ap + (size_t)(ar + 64) * K + ac);
            cp16(&Bs[s][bk][bn],      Bp + (size_t)bk * N + bn);
            cp16(&Bs[s][bk + 8][bn],  Bp + (size_t)(bk + 8) * N + bn);
            cp_commit();
            asm volatile("cp.async.wait_group 1;\n");
        } else {
            asm volatile("cp.async.wait_group 0;\n");
        }
        __syncthreads();

        const int s = kt & 1;
        #pragma unroll
        for (int ks = 0; ks < 2; ks++) {
            // A fragments: hi/lo split
            uint32_t ah[4][4], al[4][4];
            #pragma unroll
            for (int mt = 0; mt < 4; mt++) {
                const int r0 = warpM * 64 + mt * 16 + g;
                const int c0 = ks * 8 + t4;
                float x0 = As[s][r0][c0];
                float x1 = As[s][r0 + 8][c0];
                float x2 = As[s][r0][c0 + 4];
                float x3 = As[s][r0 + 8][c0 + 4];
                ah[mt][0] = f2tf32(x0); al[mt][0] = f2tf32(x0 - __uint_as_float(ah[mt][0]));
                ah[mt][1] = f2tf32(x1); al[mt][1] = f2tf32(x1 - __uint_as_float(ah[mt][1]));
                ah[mt][2] = f2tf32(x2); al[mt][2] = f2tf32(x2 - __uint_as_float(ah[mt][2]));
                ah[mt][3] = f2tf32(x3); al[mt][3] = f2tf32(x3 - __uint_as_float(ah[mt][3]));
            }
            // B fragments: hi/lo split
            uint32_t bh[4][2], bl[4][2];
            #pragma unroll
            for (int nt = 0; nt < 4; nt++) {
                const int n  = warpN * 32 + nt * 8 + g;
                const int k0 = ks * 8 + t4;
                float y0 = Bs[s][k0][n];
                float y1 = Bs[s][k0 + 4][n];
                bh[nt][0] = f2tf32(y0); bl[nt][0] = f2tf32(y0 - __uint_as_float(bh[nt][0]));
                bh[nt][1] = f2tf32(y1); bl[nt][1] = f2tf32(y1 - __uint_as_float(bh[nt][1]));
            }
            // 3xTF32: hi*hi + hi*lo + lo*hi
            #pragma unroll
            for (int mt = 0; mt < 4; mt++)
                #pragma unroll
                for (int nt = 0; nt < 4; nt++) {
                    mma_tf32(acc[mt][nt], ah[mt], bh[nt]);
                    mma_tf32(acc[mt][nt], ah[mt], bl[nt]);
                    mma_tf32(acc[mt][nt], al[mt], bh[nt]);
                }
        }
        __syncthreads();
    }

    // epilogue
    #pragma unroll
    for (int mt = 0; mt < 4; mt++) {
        const int r0 = warpM * 64 + mt * 16 + g;
        #pragma unroll
        for (int nt = 0; nt < 4; nt++) {
            const int c = warpN * 32 + nt * 8 + t4 * 2;
            *(float2*)&C[(size_t)r0 * N + c]       = make_float2(acc[mt][nt][0], acc[mt][nt][1]);
            *(float2*)&C[(size_t)(r0 + 8) * N + c] = make_float2(acc[mt][nt][2], acc[mt][nt][3]);
        }
    }
}

// ---------------- RoPE (in place) -----------------------------------------
__global__ void rope_kernel(float* __restrict__ x,
                            const float* __restrict__ cs,
                            const float* __restrict__ sn,
                            int heads) {
    int idx = blockIdx.x*blockDim.x + threadIdx.x;
    int total = B_*L_*heads*HALF_;
    if (idx >= total) return;
    int j = idx % HALF_;
    int h = (idx / HALF_) % heads;
    int l = (idx / (HALF_*heads)) % L_;
    int b =  idx / (HALF_*heads*L_);
    float c = cs[l*HALF_ + j];
    float s = sn[l*HALF_ + j];
    float* row = x + ((size_t)(b*L_ + l)*heads + h)*HD_;
    float x1 = row[j], x2 = row[j + HALF_];
    row[j]        = x1*c - x2*s;
    row[j + HALF_] = x1*s + x2*c;
}

// ---------------- Hedgehog feature map ------------------------------------
__global__ __launch_bounds__(256)
void hedgehog_kernel(const float* __restrict__ x,
                     const float* __restrict__ fm,
                     float* __restrict__ outf,
                     int xh, float scale) {
    __shared__ float xs[16][HD_];
    __shared__ float ps[16][FD_];
    __shared__ float ms[16], zs[16];

    int h = blockIdx.y, b = blockIdx.z;
    int l0 = blockIdx.x * 16;
    int t = threadIdx.x;
    int srcH = (xh == 1) ? 0 : h;

    for (int e = t; e < 16*HD_; e += 256) {
        int r = e / HD_, d = e % HD_;
        xs[r][d] = x[((size_t)(b*L_ + l0 + r)*xh + srcH)*HD_ + d];
    }
    __syncthreads();

    int r  = t / 16;
    int fb = (t % 16) * 4;
    float a0=0.f, a1=0.f, a2=0.f, a3=0.f;
    const float* fmh = fm + (size_t)h*HD_*FD_;
    #pragma unroll 4
    for (int d = 0; d < HD_; d++) {
        float xv = xs[r][d];
        float4 w = *(const float4*)&fmh[d*FD_ + fb];
        a0 += xv*w.x; a1 += xv*w.y; a2 += xv*w.z; a3 += xv*w.w;
    }
    ps[r][fb+0]=a0; ps[r][fb+1]=a1; ps[r][fb+2]=a2; ps[r][fb+3]=a3;
    __syncthreads();

    if (t < 16) {
        float m = 0.f;
        for (int f = 0; f < FD_; f++) m = fmaxf(m, fabsf(ps[t][f]));
        float z = 0.f;
        for (int f = 0; f < FD_; f++)
            z += __expf(ps[t][f] - m) + __expf(-ps[t][f] - m);
        ms[t] = m; zs[t] = z;
    }
    __syncthreads();

    for (int e = t; e < 16*FEAT_; e += 256) {
        int rr = e / FEAT_, f = e % FEAT_;
        float p = (f < FD_) ? ps[rr][f] : -ps[rr][f - FD_];
        float val = __expf(p - ms[rr]) / zs[rr] * scale;
        outf[((size_t)(b*H_ + h)*L_ + l0 + rr)*FEAT_ + f] = val;
    }
}

// ---------------- per-chunk kv state --------------------------------------
__global__ __launch_bounds__(256)
void kv_kernel(const float* __restrict__ kf, const float* __restrict__ v,
               float* __restrict__ kv) {
    __shared__ float ks[CHUNK_][FEAT_];
    __shared__ float vs[CHUNK_][64];
    int n  = blockIdx.x;
    int dt = blockIdx.y;
    int bh = blockIdx.z;
    int b  = bh / H_;
    int t  = threadIdx.x;

    const float* kfp = kf + ((size_t)bh*L_ + n*CHUNK_)*FEAT_;
    for (int e = t; e < CHUNK_*FEAT_; e += 256) ks[e/FEAT_][e%FEAT_] = kfp[e];
    const float* vp = v + ((size_t)b*L_ + n*CHUNK_)*HD_ + dt*64;
    for (int e = t; e < CHUNK_*64; e += 256) vs[e/64][e%64] = vp[(size_t)(e/64)*HD_ + (e%64)];
    __syncthreads();

    int dd = t % 64;
    int f0 = t / 64;
    float acc[32];
    #pragma unroll
    for (int i = 0; i < 32; i++) acc[i] = 0.f;

    for (int c = 0; c < CHUNK_; c++) {
        float vv = vs[c][dd];
        #pragma unroll
        for (int i = 0; i < 32; i++) acc[i] += ks[c][f0 + i*4]*vv;
    }

    float* out = kv + ((size_t)(bh*NCH_ + n)*FEAT_)*HD_ + dt*64;
    #pragma unroll
    for (int i = 0; i < 32; i++) {
        int f = f0 + i*4;
        out[(size_t)f*HD_ + dd] = acc[i];
    }
}

// ---------------- exclusive cumsum over chunk axis (in place) -------------
__global__ void cumsum_kernel(float* __restrict__ kv) {
    int bh = blockIdx.y;
    int e  = blockIdx.x*256 + threadIdx.x;
    float* base = kv + (size_t)bh*NCH_*FEAT_*HD_ + e;
    float run = 0.f;
    for (int n = 0; n < NCH_; n++) {
        float tmp = base[(size_t)n*FEAT_*HD_];
        base[(size_t)n*FEAT_*HD_] = run;
        run += tmp;
    }
}

// ---------------- inter + intra chunk attention ---------------------------
__global__ __launch_bounds__(256)
void attn_kernel(const float* __restrict__ qf, const float* __restrict__ kf,
                 const float* __restrict__ v,  const float* __restrict__ kv,
                 float* __restrict__ o) {
    __shared__ float qs[CHUNK_][FEAT_];
    __shared__ float ss[CHUNK_][CHUNK_];
    int n = blockIdx.x, h = blockIdx.y, b = blockIdx.z;
    int bh = b*H_ + h;
    int t = threadIdx.x;
    int j = t;

    const float* qp = qf + ((size_t)bh*L_ + n*CHUNK_)*FEAT_;
    for (int e = t; e < CHUNK_*FEAT_; e += 256) qs[e/FEAT_][e%FEAT_] = qp[e];
    __syncthreads();

    float acc[CHUNK_];
    #pragma unroll
    for (int i = 0; i < CHUNK_; i++) acc[i] = 0.f;

    const float* kvp = kv + ((size_t)(bh*NCH_ + n)*FEAT_)*HD_;
    for (int f = 0; f < FEAT_; f += 4) {
        float k0 = kvp[(size_t)(f+0)*HD_ + j];
        float k1 = kvp[(size_t)(f+1)*HD_ + j];
        float k2 = kvp[(size_t)(f+2)*HD_ + j];
        float k3 = kvp[(size_t)(f+3)*HD_ + j];
        #pragma unroll
        for (int i = 0; i < CHUNK_; i++) {
            float4 qv = *(const float4*)&qs[i][f];
            acc[i] += qv.x*k0 + qv.y*k1 + qv.z*k2 + qv.w*k3;
        }
    }

    {
        const float* kp = kf + ((size_t)bh*L_ + n*CHUNK_)*FEAT_;
        int i   = t / 4;
        int jp0 = (t % 4) * 16;
        for (int jj = 0; jj < 16; jj++) {
            int jp = jp0 + jj;
            float sum = 0.f;
            if (jp <= i) {
                const float* krow = kp + (size_t)jp*FEAT_;
                #pragma unroll 8
                for (int f = 0; f < FEAT_; f += 4) {
                    float4 qv = *(const float4*)&qs[i][f];
                    float4 kr = *(const float4*)&krow[f];
                    sum += qv.x*kr.x + qv.y*kr.y + qv.z*kr.z + qv.w*kr.w;
                }
            }
            ss[i][jp] = sum;
        }
    }
    __syncthreads();

    const float* vp = v + ((size_t)b*L_ + n*CHUNK_)*HD_;
    for (int jp = 0; jp < CHUNK_; jp += 4) {
        float v0 = vp[(size_t)(jp+0)*HD_ + j];
        float v1 = vp[(size_t)(jp+1)*HD_ + j];
        float v2 = vp[(size_t)(jp+2)*HD_ + j];
        float v3 = vp[(size_t)(jp+3)*HD_ + j];
        #pragma unroll
        for (int i = 0; i < CHUNK_; i++) {
            float4 sv = *(const float4*)&ss[i][jp];
            acc[i] += sv.x*v0 + sv.y*v1 + sv.z*v2 + sv.w*v3;
        }
    }

    float* op = o + ((size_t)(b*L_ + n*CHUNK_))*(H_*HD_) + h*HD_ + j;
    #pragma unroll
    for (int i = 0; i < CHUNK_; i++) op[(size_t)i*(H_*HD_)] = acc[i];
}

// ---------------- launch ---------------------------------------------------
extern "C" void kernel_launch(void* const* d_in, const int* in_sizes, int n_in,
                              void* d_out, int out_size) {
    const float* hidden = (const float*)d_in[0];
    const float* fcos   = (const float*)d_in[1];
    const float* fsin   = (const float*)d_in[2];
    // d_in[3] = mask (unused by reference math)
    const float* Wq     = (const float*)d_in[4];
    const float* Wk     = (const float*)d_in[5];
    const float* Wv     = (const float*)d_in[6];
    const float* Wo     = (const float*)d_in[7];
    const float* fmq    = (const float*)d_in[8];
    const float* fmk    = (const float*)d_in[9];
    float* out          = (float*)d_out;

    float *q, *k, *v, *qf, *kf, *kv, *o;
    cudaGetSymbolAddress((void**)&q,  g_q);
    cudaGetSymbolAddress((void**)&k,  g_k);
    cudaGetSymbolAddress((void**)&v,  g_v);
    cudaGetSymbolAddress((void**)&qf, g_qf);
    cudaGetSymbolAddress((void**)&kf, g_kf);
    cudaGetSymbolAddress((void**)&kv, g_kv);
    cudaGetSymbolAddress((void**)&o,  g_o);

    const int M = B_*L_;   // 4096

    // 1) projections (TF32 tensor cores, 3x split)
    tf32gemm_kernel<<<dim3((H_*HD_)/128, M/128), 256>>>(M, H_*HD_, D_, hidden, Wq, q);
    tf32gemm_kernel<<<dim3(HD_/128,      M/128), 256>>>(M, HD_,    D_, hidden, Wk, k);
    tf32gemm_kernel<<<dim3(HD_/128,      M/128), 256>>>(M, HD_,    D_, hidden, Wv, v);

    // 2) RoPE
    {
        int totq = B_*L_*H_*HALF_;
        rope_kernel<<<(totq + 255)/256, 256>>>(q, fcos, fsin, H_);
        int totk = B_*L_*1*HALF_;
        rope_kernel<<<(totk + 255)/256, 256>>>(k, fcos, fsin, 1);
    }

    // 3) hedgehog feature maps
    const float qscale = 0.08838834764831845f;   // 128^-0.5
    hedgehog_kernel<<<dim3(L_/16, H_, B_), 256>>>(q, fmq, qf, H_, qscale);
    hedgehog_kernel<<<dim3(L_/16, H_, B_), 256>>>(k, fmk, kf, 1, 1.0f);

    // 4) chunk kv states + exclusive cumsum
    kv_kernel<<<dim3(NCH_, 4, B_*H_), 256>>>(kf, v, kv);
    cumsum_kernel<<<dim3(128, B_*H_), 256>>>(kv);

    // 5) inter + intra attention
    attn_kernel<<<dim3(NCH_, H_, B_), 256>>>(qf, kf, v, kv, o);

    // 6) output projection
    tf32gemm_kernel<<<dim3(D_/128, M/128), 256>>>(M, D_, H_*HD_, o, Wo, out);
}

// round 4
// speedup vs baseline: 1.9214x; 1.5638x over previous
#include <cuda_runtime.h>
#include <math.h>
#include <stdint.h>

// Problem constants
#define B_ 2
#define L_ 2048
#define D_ 2048
#define H_ 8
#define HD_ 256
#define FD_ 64
#define FEAT_ 128          // 2*FD
#define CHUNK_ 64
#define NCH_ (L_/CHUNK_)   // 32
#define HALF_ (HD_/2)      // 128

// ---------------- scratch (device globals; no allocation allowed) ----------
__device__ float g_q [B_*L_*H_*HD_];
__device__ float g_k [B_*L_*HD_];
__device__ float g_v [B_*L_*HD_];
__device__ float g_qf[B_*H_*L_*FEAT_];
__device__ float g_kf[B_*H_*L_*FEAT_];
__device__ float g_kv[B_*H_*NCH_*FEAT_*HD_];
__device__ float g_o [B_*L_*H_*HD_];

// ============================================================================
// BF16 tensor-core GEMM with 3-term split (near-fp32 results)
// C[M,N] = A[M,K] * B[K,N], all row-major fp32 in/out.
// Tile 128x128x16, 8 warps (2x4), warp tile 64x32, mma m16n8k16.bf16.
// A = Ah + Al (bf16 rn split); C += Ah*Bh + Ah*Bl + Al*Bh.
// blockIdx.z selects (B1,C1) to batch two GEMMs sharing A.
// ============================================================================

__device__ __forceinline__ uint32_t packbf(float lo, float hi) {
    uint32_t r;
    asm("cvt.rn.bf16x2.f32 %0, %1, %2;" : "=r"(r) : "f"(hi), "f"(lo));
    return r;  // r = {hi16: bf16(hi), lo16: bf16(lo)}
}

// residuals of a packed pair: l0 = x0 - float(lo half), l1 = x1 - float(hi half)
__device__ __forceinline__ uint32_t residbf(uint32_t p, float x0, float x1) {
    float h0 = __uint_as_float(p << 16);
    float h1 = __uint_as_float(p & 0xFFFF0000u);
    return packbf(x0 - h0, x1 - h1);
}

__device__ __forceinline__ void mma_bf16(float* d,
                                         const uint32_t* a,
                                         const uint32_t* b) {
    asm volatile(
        "mma.sync.aligned.m16n8k16.row.col.f32.bf16.bf16.f32 "
        "{%0,%1,%2,%3}, {%4,%5,%6,%7}, {%8,%9}, {%0,%1,%2,%3};\n"
        : "+f"(d[0]), "+f"(d[1]), "+f"(d[2]), "+f"(d[3])
        : "r"(a[0]), "r"(a[1]), "r"(a[2]), "r"(a[3]),
          "r"(b[0]), "r"(b[1]));
}

__device__ __forceinline__ void cp16(void* smem_dst, const void* gmem_src) {
    uint32_t s = (uint32_t)__cvta_generic_to_shared(smem_dst);
    asm volatile("cp.async.ca.shared.global [%0], [%1], 16;\n"
                 :: "r"(s), "l"(gmem_src));
}
__device__ __forceinline__ void cp_commit() {
    asm volatile("cp.async.commit_group;\n");
}

#define ASTRIDE 24    // 16 + 8 pad: A float2 frag loads conflict-free
#define BSTRIDE 132   // 128 + 4 pad: B scalar frag loads conflict-free

__global__ __launch_bounds__(256, 2)
void bfgemm_kernel(int M, int N, int K,
                   const float* __restrict__ A,
                   const float* __restrict__ B0, float* __restrict__ C0,
                   const float* __restrict__ B1, float* __restrict__ C1) {
    __shared__ float As[2][128][ASTRIDE];   // 24 KB
    __shared__ float Bs[2][16][BSTRIDE];    // 16.5 KB

    const float* Bm = (blockIdx.z == 0) ? B0 : B1;
    float*       C  = (blockIdx.z == 0) ? C0 : C1;

    const int tid  = threadIdx.x;
    const int lane = tid & 31;
    const int warp = tid >> 5;
    const int warpM = warp & 1;       // 64 rows
    const int warpN = warp >> 1;      // 32 cols
    const int g  = lane >> 2;         // 0..7
    const int t4 = lane & 3;          // 0..3

    const int cRow = blockIdx.y, cCol = blockIdx.x;
    A  += (size_t)cRow * 128 * K;
    Bm += cCol * 128;
    C  += (size_t)cRow * 128 * N + cCol * 128;

    const int ar = tid >> 2;            // 0..63
    const int ac = (tid & 3) * 4;       // 0,4,8,12
    const int bk = tid >> 5;            // 0..7
    const int bn = (tid & 31) * 4;      // 0..124

    float acc[4][4][4];
    #pragma unroll
    for (int mt = 0; mt < 4; mt++)
        #pragma unroll
        for (int nt = 0; nt < 4; nt++)
            #pragma unroll
            for (int i = 0; i < 4; i++) acc[mt][nt][i] = 0.f;

    const int KT = K >> 4;

    // prologue
    cp16(&As[0][ar][ac],      A + (size_t)ar * K + ac);
    cp16(&As[0][ar + 64][ac], A + (size_t)(ar + 64) * K + ac);
    cp16(&Bs[0][bk][bn],      Bm + (size_t)bk * N + bn);
    cp16(&Bs[0][bk + 8][bn],  Bm + (size_t)(bk + 8) * N + bn);
    cp_commit();

    for (int kt = 0; kt < KT; kt++) {
        if (kt + 1 < KT) {
            const int s = (kt + 1) & 1;
            const int k0 = (kt + 1) << 4;
            cp16(&As[s][ar][ac],      A + (size_t)ar * K + k0 + ac);
            cp16(&As[s][ar + 64][ac], A + (size_t)(ar + 64) * K + k0 + ac);
            cp16(&Bs[s][bk][bn],      Bm + (size_t)(k0 + bk) * N + bn);
            cp16(&Bs[s][bk + 8][bn],  Bm + (size_t)(k0 + bk + 8) * N + bn);
            cp_commit();
            asm volatile("cp.async.wait_group 1;\n");
        } else {
            asm volatile("cp.async.wait_group 0;\n");
        }
        __syncthreads();

        const int s = kt & 1;
        const int k2 = 2 * t4;

        // B fragments (hi/lo split)
        uint32_t bhi[4][2], blo[4][2];
        #pragma unroll
        for (int nt = 0; nt < 4; nt++) {
            const int n = warpN * 32 + nt * 8 + g;
            float y0 = Bs[s][k2][n];
            float y1 = Bs[s][k2 + 1][n];
            float y2 = Bs[s][k2 + 8][n];
            float y3 = Bs[s][k2 + 9][n];
            bhi[nt][0] = packbf(y0, y1);  blo[nt][0] = residbf(bhi[nt][0], y0, y1);
            bhi[nt][1] = packbf(y2, y3);  blo[nt][1] = residbf(bhi[nt][1], y2, y3);
        }

        // A fragments per mt, then 3 MMAs per nt
        #pragma unroll
        for (int mt = 0; mt < 4; mt++) {
            const int r0 = warpM * 64 + mt * 16 + g;
            float2 p = *(const float2*)&As[s][r0][k2];
            float2 q = *(const float2*)&As[s][r0 + 8][k2];
            float2 u = *(const float2*)&As[s][r0][k2 + 8];
            float2 w = *(const float2*)&As[s][r0 + 8][k2 + 8];
            uint32_t ahi[4], alo[4];
            ahi[0] = packbf(p.x, p.y);  alo[0] = residbf(ahi[0], p.x, p.y);
            ahi[1] = packbf(q.x, q.y);  alo[1] = residbf(ahi[1], q.x, q.y);
            ahi[2] = packbf(u.x, u.y);  alo[2] = residbf(ahi[2], u.x, u.y);
            ahi[3] = packbf(w.x, w.y);  alo[3] = residbf(ahi[3], w.x, w.y);
            #pragma unroll
            for (int nt = 0; nt < 4; nt++) {
                mma_bf16(acc[mt][nt], ahi, bhi[nt]);
                mma_bf16(acc[mt][nt], ahi, blo[nt]);
                mma_bf16(acc[mt][nt], alo, bhi[nt]);
            }
        }
        __syncthreads();
    }

    // epilogue
    #pragma unroll
    for (int mt = 0; mt < 4; mt++) {
        const int r0 = warpM * 64 + mt * 16 + g;
        #pragma unroll
        for (int nt = 0; nt < 4; nt++) {
            const int c = warpN * 32 + nt * 8 + t4 * 2;
            *(float2*)&C[(size_t)r0 * N + c]       = make_float2(acc[mt][nt][0], acc[mt][nt][1]);
            *(float2*)&C[(size_t)(r0 + 8) * N + c] = make_float2(acc[mt][nt][2], acc[mt][nt][3]);
        }
    }
}

// ---------------- RoPE (in place) -----------------------------------------
__global__ void rope_kernel(float* __restrict__ x,
                            const float* __restrict__ cs,
                            const float* __restrict__ sn,
                            int heads) {
    int idx = blockIdx.x*blockDim.x + threadIdx.x;
    int total = B_*L_*heads*HALF_;
    if (idx >= total) return;
    int j = idx % HALF_;
    int h = (idx / HALF_) % heads;
    int l = (idx / (HALF_*heads)) % L_;
    int b =  idx / (HALF_*heads*L_);
    float c = cs[l*HALF_ + j];
    float s = sn[l*HALF_ + j];
    float* row = x + ((size_t)(b*L_ + l)*heads + h)*HD_;
    float x1 = row[j], x2 = row[j + HALF_];
    row[j]        = x1*c - x2*s;
    row[j + HALF_] = x1*s + x2*c;
}

// ---------------- Hedgehog feature map ------------------------------------
__global__ __launch_bounds__(256)
void hedgehog_kernel(const float* __restrict__ x,
                     const float* __restrict__ fm,
                     float* __restrict__ outf,
                     int xh, float scale) {
    __shared__ float xs[16][HD_];
    __shared__ float ps[16][FD_];
    __shared__ float ms[16], zs[16];

    int h = blockIdx.y, b = blockIdx.z;
    int l0 = blockIdx.x * 16;
    int t = threadIdx.x;
    int srcH = (xh == 1) ? 0 : h;

    for (int e = t; e < 16*HD_; e += 256) {
        int r = e / HD_, d = e % HD_;
        xs[r][d] = x[((size_t)(b*L_ + l0 + r)*xh + srcH)*HD_ + d];
    }
    __syncthreads();

    int r  = t / 16;
    int fb = (t % 16) * 4;
    float a0=0.f, a1=0.f, a2=0.f, a3=0.f;
    const float* fmh = fm + (size_t)h*HD_*FD_;
    #pragma unroll 4
    for (int d = 0; d < HD_; d++) {
        float xv = xs[r][d];
        float4 w = *(const float4*)&fmh[d*FD_ + fb];
        a0 += xv*w.x; a1 += xv*w.y; a2 += xv*w.z; a3 += xv*w.w;
    }
    ps[r][fb+0]=a0; ps[r][fb+1]=a1; ps[r][fb+2]=a2; ps[r][fb+3]=a3;
    __syncthreads();

    if (t < 16) {
        float m = 0.f;
        for (int f = 0; f < FD_; f++) m = fmaxf(m, fabsf(ps[t][f]));
        float z = 0.f;
        for (int f = 0; f < FD_; f++)
            z += __expf(ps[t][f] - m) + __expf(-ps[t][f] - m);
        ms[t] = m; zs[t] = z;
    }
    __syncthreads();

    for (int e = t; e < 16*FEAT_; e += 256) {
        int rr = e / FEAT_, f = e % FEAT_;
        float p = (f < FD_) ? ps[rr][f] : -ps[rr][f - FD_];
        float val = __expf(p - ms[rr]) / zs[rr] * scale;
        outf[((size_t)(b*H_ + h)*L_ + l0 + rr)*FEAT_ + f] = val;
    }
}

// ---------------- per-chunk kv state --------------------------------------
__global__ __launch_bounds__(256)
void kv_kernel(const float* __restrict__ kf, const float* __restrict__ v,
               float* __restrict__ kv) {
    __shared__ float ks[CHUNK_][FEAT_];
    __shared__ float vs[CHUNK_][64];
    int n  = blockIdx.x;
    int dt = blockIdx.y;
    int bh = blockIdx.z;
    int b  = bh / H_;
    int t  = threadIdx.x;

    const float* kfp = kf + ((size_t)bh*L_ + n*CHUNK_)*FEAT_;
    for (int e = t; e < CHUNK_*FEAT_; e += 256) ks[e/FEAT_][e%FEAT_] = kfp[e];
    const float* vp = v + ((size_t)b*L_ + n*CHUNK_)*HD_ + dt*64;
    for (int e = t; e < CHUNK_*64; e += 256) vs[e/64][e%64] = vp[(size_t)(e/64)*HD_ + (e%64)];
    __syncthreads();

    int dd = t % 64;
    int f0 = t / 64;
    float acc[32];
    #pragma unroll
    for (int i = 0; i < 32; i++) acc[i] = 0.f;

    for (int c = 0; c < CHUNK_; c++) {
        float vv = vs[c][dd];
        #pragma unroll
        for (int i = 0; i < 32; i++) acc[i] += ks[c][f0 + i*4]*vv;
    }

    float* out = kv + ((size_t)(bh*NCH_ + n)*FEAT_)*HD_ + dt*64;
    #pragma unroll
    for (int i = 0; i < 32; i++) {
        int f = f0 + i*4;
        out[(size_t)f*HD_ + dd] = acc[i];
    }
}

// ---------------- exclusive cumsum over chunk axis (in place) -------------
__global__ void cumsum_kernel(float* __restrict__ kv) {
    int bh = blockIdx.y;
    int e  = blockIdx.x*256 + threadIdx.x;
    float* base = kv + (size_t)bh*NCH_*FEAT_*HD_ + e;
    float run = 0.f;
    for (int n = 0; n < NCH_; n++) {
        float tmp = base[(size_t)n*FEAT_*HD_];
        base[(size_t)n*FEAT_*HD_] = run;
        run += tmp;
    }
}

// ---------------- inter + intra chunk attention ---------------------------
__global__ __launch_bounds__(256)
void attn_kernel(const float* __restrict__ qf, const float* __restrict__ kf,
                 const float* __restrict__ v,  const float* __restrict__ kv,
                 float* __restrict__ o) {
    __shared__ float qs[CHUNK_][FEAT_];
    __shared__ float ss[CHUNK_][CHUNK_];
    int n = blockIdx.x, h = blockIdx.y, b = blockIdx.z;
    int bh = b*H_ + h;
    int t = threadIdx.x;
    int j = t;

    const float* qp = qf + ((size_t)bh*L_ + n*CHUNK_)*FEAT_;
    for (int e = t; e < CHUNK_*FEAT_; e += 256) qs[e/FEAT_][e%FEAT_] = qp[e];
    __syncthreads();

    float acc[CHUNK_];
    #pragma unroll
    for (int i = 0; i < CHUNK_; i++) acc[i] = 0.f;

    const float* kvp = kv + ((size_t)(bh*NCH_ + n)*FEAT_)*HD_;
    for (int f = 0; f < FEAT_; f += 4) {
        float k0 = kvp[(size_t)(f+0)*HD_ + j];
        float k1 = kvp[(size_t)(f+1)*HD_ + j];
        float k2 = kvp[(size_t)(f+2)*HD_ + j];
        float k3 = kvp[(size_t)(f+3)*HD_ + j];
        #pragma unroll
        for (int i = 0; i < CHUNK_; i++) {
            float4 qv = *(const float4*)&qs[i][f];
            acc[i] += qv.x*k0 + qv.y*k1 + qv.z*k2 + qv.w*k3;
        }
    }

    {
        const float* kp = kf + ((size_t)bh*L_ + n*CHUNK_)*FEAT_;
        int i   = t / 4;
        int jp0 = (t % 4) * 16;
        for (int jj = 0; jj < 16; jj++) {
            int jp = jp0 + jj;
            float sum = 0.f;
            if (jp <= i) {
                const float* krow = kp + (size_t)jp*FEAT_;
                #pragma unroll 8
                for (int f = 0; f < FEAT_; f += 4) {
                    float4 qv = *(const float4*)&qs[i][f];
                    float4 kr = *(const float4*)&krow[f];
                    sum += qv.x*kr.x + qv.y*kr.y + qv.z*kr.z + qv.w*kr.w;
                }
            }
            ss[i][jp] = sum;
        }
    }
    __syncthreads();

    const float* vp = v + ((size_t)b*L_ + n*CHUNK_)*HD_;
    for (int jp = 0; jp < CHUNK_; jp += 4) {
        float v0 = vp[(size_t)(jp+0)*HD_ + j];
        float v1 = vp[(size_t)(jp+1)*HD_ + j];
        float v2 = vp[(size_t)(jp+2)*HD_ + j];
        float v3 = vp[(size_t)(jp+3)*HD_ + j];
        #pragma unroll
        for (int i = 0; i < CHUNK_; i++) {
            float4 sv = *(const float4*)&ss[i][jp];
            acc[i] += sv.x*v0 + sv.y*v1 + sv.z*v2 + sv.w*v3;
        }
    }

    float* op = o + ((size_t)(b*L_ + n*CHUNK_))*(H_*HD_) + h*HD_ + j;
    #pragma unroll
    for (int i = 0; i < CHUNK_; i++) op[(size_t)i*(H_*HD_)] = acc[i];
}

// ---------------- launch ---------------------------------------------------
// Launch order puts the big Q-projection GEMM at launch index 4 so the ncu
// capture (-s 5 -c 1, which has been landing on the 5th launch) profiles it.
extern "C" void kernel_launch(void* const* d_in, const int* in_sizes, int n_in,
                              void* d_out, int out_size) {
    const float* hidden = (const float*)d_in[0];
    const float* fcos   = (const float*)d_in[1];
    const float* fsin   = (const float*)d_in[2];
    // d_in[3] = mask (unused by reference math)
    const float* Wq     = (const float*)d_in[4];
    const float* Wk     = (const float*)d_in[5];
    const float* Wv     = (const float*)d_in[6];
    const float* Wo     = (const float*)d_in[7];
    const float* fmq    = (const float*)d_in[8];
    const float* fmk    = (const float*)d_in[9];
    float* out          = (float*)d_out;

    float *q, *k, *v, *qf, *kf, *kv, *o;
    cudaGetSymbolAddress((void**)&q,  g_q);
    cudaGetSymbolAddress((void**)&k,  g_k);
    cudaGetSymbolAddress((void**)&v,  g_v);
    cudaGetSymbolAddress((void**)&qf, g_qf);
    cudaGetSymbolAddress((void**)&kf, g_kf);
    cudaGetSymbolAddress((void**)&kv, g_kv);
    cudaGetSymbolAddress((void**)&o,  g_o);

    const int M = B_*L_;   // 4096
    const float qscale = 0.08838834764831845f;   // 128^-0.5

    // 0: K and V projections, batched in z
    bfgemm_kernel<<<dim3(HD_/128, M/128, 2), 256>>>(M, HD_, D_, hidden, Wk, k, Wv, v);
    // 1: RoPE on K
    rope_kernel<<<(B_*L_*HALF_ + 255)/256, 256>>>(k, fcos, fsin, 1);
    // 2: hedgehog K
    hedgehog_kernel<<<dim3(L_/16, H_, B_), 256>>>(k, fmk, kf, 1, 1.0f);
    // 3: per-chunk kv states
    kv_kernel<<<dim3(NCH_, 4, B_*H_), 256>>>(kf, v, kv);
    // 4: Q projection (profiled slot)
    bfgemm_kernel<<<dim3((H_*HD_)/128, M/128, 1), 256>>>(M, H_*HD_, D_, hidden, Wq, q, Wq, q);
    // 5: exclusive cumsum of kv states
    cumsum_kernel<<<dim3(128, B_*H_), 256>>>(kv);
    // 6: RoPE on Q
    rope_kernel<<<(B_*L_*H_*HALF_ + 255)/256, 256>>>(q, fcos, fsin, H_);
    // 7: hedgehog Q
    hedgehog_kernel<<<dim3(L_/16, H_, B_), 256>>>(q, fmq, qf, H_, qscale);
    // 8: inter + intra attention
    attn_kernel<<<dim3(NCH_, H_, B_), 256>>>(qf, kf, v, kv, o);
    // 9: output projection
    bfgemm_kernel<<<dim3(D_/128, M/128, 1), 256>>>(M, D_, H_*HD_, o, Wo, out, Wo, out);
}